// round 13
// baseline (speedup 1.0000x reference)
#include <cuda_runtime.h>
#include <cuda_bf16.h>
#include <math.h>
#include <stdint.h>

#define NB 64
#define NS 256
#define NU 1024
#define NT 512
#define NTH 512
#define NBS (NB * NS)

__device__ __nv_bfloat16 g_h_h[NBS * NU], g_h_l[NBS * NU];
__device__ __nv_bfloat16 g_hpt[NBS * NU];                     // [u][b*256+s]
__device__ __nv_bfloat16 g_Wt1q_h[2048 * NU], g_Wt1q_l[2048 * NU];
__device__ __nv_bfloat16 g_Wy2t_h[NT * NU],   g_Wy2t_l[NT * NU];
__device__ __nv_bfloat16 g_Wgt_h[4096 * 1536], g_Wgt_l[4096 * 1536];
__device__ __nv_bfloat16 g_We1t_h[NU * NU],   g_We1t_l[NU * NU];
__device__ __nv_bfloat16 g_t1_h[NB * NU], g_t1_l[NB * NU];    // [b][u]
__device__ __nv_bfloat16 g_s_h[NB * NU],  g_s_l[NB * NU];     // [b][u]
__device__ float g_y32[NB * NT];                              // [b][m], atomically built
__device__ float g_q[NB * NU], g_c[NB * NU];
__device__ float g_e[NB * NS];
__device__ float g_gt[NB * 4096];
__device__ float2 g_lut_sig[2049], g_lut_tanh[2049];
__device__ unsigned g_cnt, g_phs;

#define O_LS 0
#define O_LT 16392
#define O_WK 32784
#define O_AH 44032
#define O_AL 52224
#define O_BH 60416
#define O_BL 68608
#define PSMEM 76800

#define SWZ(x) ((x) ^ (((x) >> 3) & 0x70))

__device__ __forceinline__ uint32_t smem_u32(const void* p) {
    uint32_t a;
    asm("{ .reg .u64 t; cvta.to.shared.u64 t, %1; cvt.u32.u64 %0, t; }" : "=r"(a) : "l"(p));
    return a;
}
__device__ __forceinline__ void ldsm4(uint32_t* r, uint32_t addr) {
    asm volatile("ldmatrix.sync.aligned.m8n8.x4.shared.b16 {%0,%1,%2,%3}, [%4];"
        : "=r"(r[0]), "=r"(r[1]), "=r"(r[2]), "=r"(r[3]) : "r"(addr));
}
__device__ __forceinline__ void hmma(float* d, const uint32_t* a, uint32_t b0, uint32_t b1) {
    asm volatile("mma.sync.aligned.m16n8k16.row.col.f32.bf16.bf16.f32 "
        "{%0,%1,%2,%3}, {%4,%5,%6,%7}, {%8,%9}, {%0,%1,%2,%3};"
        : "+f"(d[0]), "+f"(d[1]), "+f"(d[2]), "+f"(d[3])
        : "r"(a[0]), "r"(a[1]), "r"(a[2]), "r"(a[3]), "r"(b0), "r"(b1));
}
__device__ __forceinline__ float lut_eval(const float2* __restrict__ lut, float x) {
    float xc = fminf(fmaxf(x, -8.0f), 8.0f);
    float f  = fmaf(xc, 128.0f, 1024.0f);
    float m  = (f - 0.5f) + 12582912.0f;
    int  idx = __float_as_int(m) - 0x4B400000;
    float2 p = lut[idx];
    return fmaf(f - (m - 12582912.0f), p.y, p.x);
}
__device__ __forceinline__ void hilo(float v, __nv_bfloat16* hp, __nv_bfloat16* lp) {
    __nv_bfloat16 h = __float2bfloat16(v);
    *hp = h;
    *lp = __float2bfloat16(v - __bfloat162float(h));
}
__device__ __forceinline__ uint4 pack8(const float* v, bool hi) {
    uint16_t r[8];
#pragma unroll
    for (int j = 0; j < 8; j++) {
        __nv_bfloat16 hh = __float2bfloat16(v[j]);
        __nv_bfloat16 e  = hi ? hh : __float2bfloat16(v[j] - __bfloat162float(hh));
        r[j] = *(uint16_t*)&e;
    }
    return *(uint4*)r;
}
__device__ __forceinline__ void gsync(unsigned& tgt) {
    tgt++;
    __syncthreads();
    if (threadIdx.x == 0) {
        __threadfence();
        if (atomicAdd(&g_cnt, 1u) == gridDim.x - 1) {
            g_cnt = 0; __threadfence(); atomicExch(&g_phs, tgt);
        } else {
            while (*(volatile unsigned*)&g_phs < tgt) { }
        }
    }
    __syncthreads();
}

__global__ void k_init() {
    int tid = threadIdx.x;
    if (tid == 0) { g_cnt = 0; g_phs = 0; }
    for (int i = tid; i < 2049; i += NTH) {
        float x0 = -8.0f + i * (1.0f / 128.0f), x1 = x0 + (1.0f / 128.0f);
        float sa = 1.0f / (1.0f + expf(-x0));
        float sb = (i == 2048) ? sa : 1.0f / (1.0f + expf(-x1));
        g_lut_sig[i] = make_float2(sa, sb - sa);
        float ta = tanhf(x0), tb = (i == 2048) ? ta : tanhf(x1);
        g_lut_tanh[i] = make_float2(ta, tb - ta);
    }
}

// D[64 x 64] = A[m0..+64][K](hi/lo) @ B[64][K](hi/lo)^T, 3-term hi/lo bf16 HMMA.
__device__ __forceinline__ void mma_job(
    char* dyn, uint32_t su,
    const __nv_bfloat16* aH, const __nv_bfloat16* aL, int lda,
    const __nv_bfloat16* bH, const __nv_bfloat16* bL, int ldb,
    int nch, float acc[2][4])
{
    const int tid = threadIdx.x, lane = tid & 31, warp = tid >> 5;
    const int wm = warp >> 2, wn = warp & 3;
    const int sr = tid >> 3, ss = tid & 7;
    const int arow = wm * 16 + (lane & 15), ablk = lane >> 4;
    const int brow = wn * 16 + (lane & 7) + ((lane >> 4) << 3), bblk = (lane >> 3) & 1;
    const uint32_t soff = SWZ((uint32_t)(sr * 128 + ss * 16));

    uint4 vah = *(const uint4*)(aH + (size_t)sr * lda + ss * 8);
    uint4 val = *(const uint4*)(aL + (size_t)sr * lda + ss * 8);
    uint4 vbh = __ldcg((const uint4*)(bH + (size_t)sr * ldb + ss * 8));
    uint4 vbl = __ldcg((const uint4*)(bL + (size_t)sr * ldb + ss * 8));

    for (int c = 0; c < nch; c++) {
        __syncthreads();
        *(uint4*)(dyn + O_AH + soff) = vah;
        *(uint4*)(dyn + O_AL + soff) = val;
        *(uint4*)(dyn + O_BH + soff) = vbh;
        *(uint4*)(dyn + O_BL + soff) = vbl;
        __syncthreads();
        if (c + 1 < nch) {
            int k = (c + 1) * 64 + ss * 8;
            vah = *(const uint4*)(aH + (size_t)sr * lda + k);
            val = *(const uint4*)(aL + (size_t)sr * lda + k);
            vbh = __ldcg((const uint4*)(bH + (size_t)sr * ldb + k));
            vbl = __ldcg((const uint4*)(bL + (size_t)sr * ldb + k));
        }
#pragma unroll
        for (int ks = 0; ks < 4; ks++) {
            uint32_t ao = SWZ((uint32_t)(arow * 128 + ks * 32 + ablk * 16));
            uint32_t bo = SWZ((uint32_t)(brow * 128 + ks * 32 + bblk * 16));
            uint32_t ah[4], al[4], bh[4], bl[4];
            ldsm4(ah, su + O_AH + ao);
            ldsm4(al, su + O_AL + ao);
            ldsm4(bh, su + O_BH + bo);
            ldsm4(bl, su + O_BL + bo);
            hmma(acc[0], ah, bh[0], bh[1]);
            hmma(acc[1], ah, bh[2], bh[3]);
            hmma(acc[0], ah, bl[0], bl[1]);
            hmma(acc[1], ah, bl[2], bl[3]);
            hmma(acc[0], al, bh[0], bh[1]);
            hmma(acc[1], al, bh[2], bh[3]);
        }
    }
}

// Same, but B source is fp32 (converted to hi/lo on the fly).
// FIX vs R11: every thread stores BOTH the hi and lo pack of its row segment
// (previously rows 32-63 of B-hi and rows 0-31 of B-lo were stale garbage).
__device__ __forceinline__ void mma_job_f32b(
    char* dyn, uint32_t su,
    const __nv_bfloat16* aH, const __nv_bfloat16* aL, int lda,
    const float* bF, int ldb, int nch, float acc[2][4])
{
    const int tid = threadIdx.x, lane = tid & 31, warp = tid >> 5;
    const int wm = warp >> 2, wn = warp & 3;
    const int sr = tid >> 3, ss = tid & 7;
    const int arow = wm * 16 + (lane & 15), ablk = lane >> 4;
    const int brow = wn * 16 + (lane & 7) + ((lane >> 4) << 3), bblk = (lane >> 3) & 1;
    const uint32_t soff = SWZ((uint32_t)(sr * 128 + ss * 16));

    uint4 vah = *(const uint4*)(aH + (size_t)sr * lda + ss * 8);
    uint4 val = *(const uint4*)(aL + (size_t)sr * lda + ss * 8);
    float fb[8];
    {
        float4 f0 = __ldcg((const float4*)(bF + (size_t)sr * ldb + ss * 8));
        float4 f1 = __ldcg((const float4*)(bF + (size_t)sr * ldb + ss * 8 + 4));
        fb[0] = f0.x; fb[1] = f0.y; fb[2] = f0.z; fb[3] = f0.w;
        fb[4] = f1.x; fb[5] = f1.y; fb[6] = f1.z; fb[7] = f1.w;
    }
    for (int c = 0; c < nch; c++) {
        uint4 vbh = pack8(fb, true);
        uint4 vbl = pack8(fb, false);
        __syncthreads();
        *(uint4*)(dyn + O_AH + soff) = vah;
        *(uint4*)(dyn + O_AL + soff) = val;
        *(uint4*)(dyn + O_BH + soff) = vbh;
        *(uint4*)(dyn + O_BL + soff) = vbl;
        __syncthreads();
        if (c + 1 < nch) {
            int k = (c + 1) * 64 + ss * 8;
            vah = *(const uint4*)(aH + (size_t)sr * lda + k);
            val = *(const uint4*)(aL + (size_t)sr * lda + k);
            float4 f0 = __ldcg((const float4*)(bF + (size_t)sr * ldb + k));
            float4 f1 = __ldcg((const float4*)(bF + (size_t)sr * ldb + k + 4));
            fb[0] = f0.x; fb[1] = f0.y; fb[2] = f0.z; fb[3] = f0.w;
            fb[4] = f1.x; fb[5] = f1.y; fb[6] = f1.z; fb[7] = f1.w;
        }
#pragma unroll
        for (int ks = 0; ks < 4; ks++) {
            uint32_t ao = SWZ((uint32_t)(arow * 128 + ks * 32 + ablk * 16));
            uint32_t bo = SWZ((uint32_t)(brow * 128 + ks * 32 + bblk * 16));
            uint32_t ah[4], al[4], bh[4], bl[4];
            ldsm4(ah, su + O_AH + ao);
            ldsm4(al, su + O_AL + ao);
            ldsm4(bh, su + O_BH + bo);
            ldsm4(bl, su + O_BL + bo);
            hmma(acc[0], ah, bh[0], bh[1]);
            hmma(acc[1], ah, bh[2], bh[3]);
            hmma(acc[0], ah, bl[0], bl[1]);
            hmma(acc[1], ah, bl[2], bl[3]);
            hmma(acc[0], al, bh[0], bh[1]);
            hmma(acc[1], al, bh[2], bh[3]);
        }
    }
}
#define EPI_LOOP(body) do {                                                     \
    const int _wm = (threadIdx.x >> 7), _wn = (threadIdx.x >> 5) & 3;           \
    const int _tq = (threadIdx.x & 31) >> 2, _tr = threadIdx.x & 3;             \
    _Pragma("unroll") for (int _i = 0; _i < 2; _i++) {                          \
        int ml = _wm * 16 + _tq + _i * 8;                                       \
        _Pragma("unroll") for (int _na = 0; _na < 2; _na++)                     \
        _Pragma("unroll") for (int _j = 0; _j < 2; _j++) {                      \
            int nl = _wn * 16 + _na * 8 + _tr * 2 + _j;                         \
            float v = acc[_na][_i * 2 + _j];                                    \
            body                                                                 \
        }                                                                        \
    }                                                                            \
} while (0)

__global__ __launch_bounds__(NTH, 1) void k_all(
    const float* __restrict__ h,  const float* __restrict__ s0,
    const float* __restrict__ Wy1, const float* __restrict__ by1,
    const float* __restrict__ Wy2, const float* __restrict__ by2,
    const float* __restrict__ We1, const float* __restrict__ be1,
    const float* __restrict__ We2, const float* __restrict__ be2,
    const float* __restrict__ Wi,  const float* __restrict__ bi,
    const float* __restrict__ Wf,  const float* __restrict__ bf,
    const float* __restrict__ Wg,  const float* __restrict__ bg,
    const float* __restrict__ Wo,  const float* __restrict__ bo,
    float* __restrict__ out)
{
    extern __shared__ char dyn[];
    float2* lsig  = (float2*)(dyn + O_LS);
    float2* ltanh = (float2*)(dyn + O_LT);
    float*  work  = (float*)(dyn + O_WK);
    const uint32_t su = smem_u32(dyn);
    const int tid = threadIdx.x, bid = blockIdx.x;
    const int gth = gridDim.x * NTH, gid = bid * NTH + tid;
    unsigned tgt = 0;

    for (int i = tid; i < 2049; i += NTH) { lsig[i] = g_lut_sig[i]; ltanh[i] = g_lut_tanh[i]; }
    __syncthreads();
    const float be2v = be2[0];

    // ---- A1: conversions + weight transposes (hi/lo) ----
    for (size_t i = gid; i < (size_t)NBS * NU; i += gth)
        hilo(__ldcs(h + i), g_h_h + i, g_h_l + i);
    for (int i = gid; i < 2048 * NU; i += gth) {
        int k = i >> 11, m = i & 2047;
        float v = (m < NU) ? Wy1[(size_t)k * NU + m] : We1[(size_t)(NU + k) * NU + (m - NU)];
        hilo(v, g_Wt1q_h + (size_t)m * NU + k, g_Wt1q_l + (size_t)m * NU + k);
    }
    for (int i = gid; i < NT * NU; i += gth) {
        int k = i >> 9, m = i & 511;
        hilo(Wy2[(size_t)k * NT + m], g_Wy2t_h + (size_t)m * NU + k, g_Wy2t_l + (size_t)m * NU + k);
    }
    for (int i = gid; i < 4096 * 1536; i += gth) {
        int k = i >> 12, m = i & 4095, gate = m >> 10, u = m & 1023;
        const float* W = (gate == 0) ? Wi : (gate == 1) ? Wf : (gate == 2) ? Wg : Wo;
        hilo(W[(size_t)k * NU + u], g_Wgt_h + (size_t)m * 1536 + k, g_Wgt_l + (size_t)m * 1536 + k);
    }
    for (int i = gid; i < NU * NU; i += gth) {
        int k = i >> 10, m = i & 1023;
        hilo(We1[(size_t)k * NU + m], g_We1t_h + (size_t)m * NU + k, g_We1t_l + (size_t)m * NU + k);
    }
    for (int i = gid; i < NB * NU; i += gth)
        hilo(s0[i], g_s_h + i, g_s_l + i);
    for (int i = gid; i < NB * NT; i += gth)
        g_y32[i] = by2[i & 511];
    gsync(tgt);

    // ---- A2: hproj = We1h^T @ h^T -> g_hpt[u][bs]  (4096 jobs) ----
    for (int j = bid; j < 4096; j += gridDim.x) {
        int m0 = (j >> 8) * 64, n0 = (j & 255) * 64;
        float acc[2][4] = {};
        mma_job(dyn, su, g_We1t_h + (size_t)m0 * NU, g_We1t_l + (size_t)m0 * NU, NU,
                g_h_h + (size_t)n0 * NU, g_h_l + (size_t)n0 * NU, NU, 16, acc);
        EPI_LOOP({
            g_hpt[(size_t)(m0 + ml) * NBS + n0 + nl] = __float2bfloat16(v);
        });
    }
    gsync(tgt);

    // =========================== scan (4 barriers/step) ===========================
    for (int t = 0; t < NS; t++) {
        // P1: t1q (bids 0-31, K=1024) + gates-s partial (bids 32-95, K=1024) + zero e
        if (bid < 32) {
            int m0 = bid * 64;
            float acc[2][4] = {};
            mma_job(dyn, su, g_Wt1q_h + (size_t)m0 * NU, g_Wt1q_l + (size_t)m0 * NU, NU,
                    g_s_h, g_s_l, NU, 16, acc);
            EPI_LOOP({
                int m = m0 + ml;
                if (m < NU) {
                    float tv = lut_eval(ltanh, v + by1[m]);
                    hilo(tv, g_t1_h + nl * NU + m, g_t1_l + nl * NU + m);
                } else {
                    g_q[nl * NU + (m - NU)] = v + be1[m - NU];
                }
            });
        } else if (bid < 96) {
            int m0 = (bid - 32) * 64;
            float acc[2][4] = {};
            mma_job(dyn, su, g_Wgt_h + (size_t)m0 * 1536 + 512,
                    g_Wgt_l + (size_t)m0 * 1536 + 512, 1536,
                    g_s_h, g_s_l, NU, 16, acc);
            EPI_LOOP({
                g_gt[nl * 4096 + m0 + ml] = v;
            });
        } else if (bid < 128) {
            g_e[(bid - 96) * NTH + tid] = 0.f;
        }
        gsync(tgt);

        // P2: y split-K (bids 0-15) + energy partial dots (bids 16-143)
        if (bid < 16) {
            int m0 = (bid >> 1) * 64, kh = bid & 1;
            float acc[2][4] = {};
            mma_job(dyn, su, g_Wy2t_h + (size_t)m0 * NU + kh * 512,
                    g_Wy2t_l + (size_t)m0 * NU + kh * 512, NU,
                    g_t1_h + kh * 512, g_t1_l + kh * 512, NU, 8, acc);
            EPI_LOOP({
                atomicAdd(&g_y32[nl * NT + m0 + ml], v);
            });
        } else if (bid < 144) {
            int e = bid - 16, b = e >> 1, uh = e & 1;
            float2* swq = (float2*)work;
            {
                int u = uh * 512 + tid;
                swq[tid] = make_float2(__ldcg(g_q + b * NU + u), We2[u]);
            }
            __syncthreads();
            int s = tid & 255, up = tid >> 8;
            const unsigned short* hp = (const unsigned short*)g_hpt +
                                       (size_t)(uh * 512 + up * 256) * NBS + b * NS + s;
            float av = 0.f;
#pragma unroll 8
            for (int u = 0; u < 256; u++) {
                unsigned short raw = __ldcg(hp + (size_t)u * NBS);
                float hv = __int_as_float((int)((unsigned)raw << 16));
                float2 qw = swq[up * 256 + u];
                av = fmaf(lut_eval(lsig, hv + qw.x), qw.y, av);
            }
            float* ew = work + 1024;
            ew[tid] = av;
            __syncthreads();
            if (tid < 256) atomicAdd(&g_e[b * NS + tid], ew[tid] + ew[tid + 256]);
        }
        gsync(tgt);

        // P4: gates-y (bids 0-63, K=512, fp32 B) + context w/ local softmax (64-127)
        if (bid < 64) {
            int m0 = bid * 64;
            float acc[2][4] = {};
            mma_job_f32b(dyn, su, g_Wgt_h + (size_t)m0 * 1536,
                         g_Wgt_l + (size_t)m0 * 1536, 1536,
                         g_y32, NT, 8, acc);
            EPI_LOOP({
                int gi = nl * 4096 + m0 + ml;
                g_gt[gi] = v + __ldcg(g_gt + gi);
            });
        } else if (bid < 128) {
            int b = bid - 64;
            float ev = (tid < NS) ? lut_eval(lsig, __ldcg(g_e + b * NS + tid) + be2v) : -1e30f;
            work[tid] = ev;
            __syncthreads();
            for (int o = 256; o > 0; o >>= 1) {
                if (tid < o) work[tid] = fmaxf(work[tid], work[tid + o]);
                __syncthreads();
            }
            float mx = work[0];
            __syncthreads();
            float p = expf(ev - mx);
            work[tid] = p;
            __syncthreads();
            for (int o = 256; o > 0; o >>= 1) {
                if (tid < o) work[tid] += work[tid + o];
                __syncthreads();
            }
            float rinv = 1.0f / work[0];
            float* aw = work + 512;
            if (tid < NS) aw[tid] = p * rinv;
            __syncthreads();
            const unsigned* hb = (const unsigned*)(g_h_h + (size_t)b * NS * NU) + tid;
            float a0 = 0.f, a1 = 0.f, a2 = 0.f, a3 = 0.f;
#pragma unroll 4
            for (int s2 = 0; s2 < NS; s2 += 2) {
                unsigned r0 = __ldcg(hb + (size_t)(s2 + 0) * (NU / 2));
                unsigned r1 = __ldcg(hb + (size_t)(s2 + 1) * (NU / 2));
                float w0 = aw[s2], w1 = aw[s2 + 1];
                a0 = fmaf(__int_as_float((int)(r0 << 16)), w0, a0);
                a1 = fmaf(__int_as_float((int)(r0 & 0xFFFF0000u)), w0, a1);
                a2 = fmaf(__int_as_float((int)(r1 << 16)), w1, a2);
                a3 = fmaf(__int_as_float((int)(r1 & 0xFFFF0000u)), w1, a3);
            }
            g_c[b * NU + 2 * tid]     = a0 + a2;
            g_c[b * NU + 2 * tid + 1] = a1 + a3;
        }
        gsync(tgt);

        // P5: write y to out + reseed g_y32; s' = o * tanh(f*c + i*g)
        for (int i = gid; i < NB * NT; i += gth) {
            int n = i >> 9, m = i & 511;
            out[((size_t)n * NS + t) * NT + m] = __ldcg(g_y32 + i);
            g_y32[i] = by2[m];
        }
        for (int i = gid; i < NB * NU; i += gth) {
            int b = i >> 10, u = i & 1023;
            const float* gp = g_gt + b * 4096 + u;
            float iv = lut_eval(lsig,  __ldcg(gp)        + bi[u]);
            float fv = lut_eval(lsig,  __ldcg(gp + 1024) + bf[u]);
            float gv = lut_eval(ltanh, __ldcg(gp + 2048) + bg[u]);
            float ov = lut_eval(lsig,  __ldcg(gp + 3072) + bo[u]);
            float cv = __ldcg(g_c + i);
            float sv = ov * lut_eval(ltanh, fmaf(fv, cv, iv * gv));
            hilo(sv, g_s_h + i, g_s_l + i);
        }
        gsync(tgt);
    }
}

extern "C" void kernel_launch(void* const* d_in, const int* in_sizes, int n_in,
                              void* d_out, int out_size) {
    (void)in_sizes; (void)n_in; (void)out_size;
    const float* h   = (const float*)d_in[0];
    const float* s0  = (const float*)d_in[1];
    const float* Wy1 = (const float*)d_in[2];
    const float* by1 = (const float*)d_in[3];
    const float* Wy2 = (const float*)d_in[4];
    const float* by2 = (const float*)d_in[5];
    const float* We1 = (const float*)d_in[6];
    const float* be1 = (const float*)d_in[7];
    const float* We2 = (const float*)d_in[8];
    const float* be2 = (const float*)d_in[9];
    const float* Wf  = (const float*)d_in[10];
    const float* bf  = (const float*)d_in[11];
    const float* Wi  = (const float*)d_in[12];
    const float* bi  = (const float*)d_in[13];
    const float* Wg  = (const float*)d_in[14];
    const float* bg  = (const float*)d_in[15];
    const float* Wo  = (const float*)d_in[16];
    const float* bo  = (const float*)d_in[17];
    float* out = (float*)d_out;

    int nsm = 148;
    cudaDeviceGetAttribute(&nsm, cudaDevAttrMultiProcessorCount, 0);
    static int sset = 0;
    if (!sset) {
        cudaFuncSetAttribute(k_all, cudaFuncAttributeMaxDynamicSharedMemorySize, PSMEM);
        sset = 1;
    }
    k_init<<<1, NTH>>>();
    k_all<<<nsm, NTH, PSMEM>>>(h, s0, Wy1, by1, Wy2, by2, We1, be1, We2, be2,
                               Wi, bi, Wf, bf, Wg, bg, Wo, bo, out);
}